// round 4
// baseline (speedup 1.0000x reference)
#include <cuda_runtime.h>
#include <cuda_fp16.h>

#define N_NODES 50000
#define N_EDGES 800000
#define PREP_BLOCKS 391     // ceil(800000/2048)
#define SCAN_BLOCKS 196     // ceil(50000/256)
#define GEMM_BLOCKS 1563    // ceil(50000/32)

// ---------------- scratch (static device globals; no allocation) ----------------
__device__ __align__(16) int   g_src[N_EDGES];
__device__ __align__(16) int   g_dst[N_EDGES];
__device__ int   g_cnt[N_NODES];                 // zero at start of every replay (invariant)
__device__ int   g_scan[SCAN_BLOCKS * 256];
__device__ int   g_btot[SCAN_BLOCKS];
__device__ int   g_off[N_NODES + 1];
__device__ int   g_cur[N_NODES];
__device__ __align__(16) int     g_ssrc[N_EDGES];
__device__ __align__(16) float   g_salpha[N_EDGES * 4];    // partial logits (no adst), 12.8 MB
__device__ __align__(16) __half2 g_x2[N_NODES * 128];      // x in fp16, 25.6 MB
__device__ __align__(16) float   g_asrc[N_NODES * 4];
__device__ __align__(16) float   g_adst[N_NODES * 4];
__device__ __align__(16) __half  g_WhT[256 * 64];          // W transposed [n][k], fp16
__device__ float g_v[12];                                  // [edim*4 + head]

// ================= K1: prep (detect+unpack+hist) + W convert + v_edge =================
__global__ void __launch_bounds__(256) k_prep_wconv(const unsigned* __restrict__ p,
                                                    const float* __restrict__ W,
                                                    const float* __restrict__ W_edge,
                                                    const float* __restrict__ att_edge) {
    int b = blockIdx.x, t = threadIdx.x;
    if (b < PREP_BLOCKS) {
        // --- block-local int64/int32 detection over this block's 2048 edges ---
        __shared__ unsigned wacc[8];
        __shared__ int s_is64;
        int base = b * 2048;
        unsigned acc = 0;
#pragma unroll
        for (int i = 0; i < 8; i++) {
            int e = base + t + 256 * i;
            if (e < N_EDGES) acc |= p[2 * e + 1];
        }
#pragma unroll
        for (int o = 16; o; o >>= 1) acc |= __shfl_xor_sync(0xffffffffu, acc, o);
        if ((t & 31) == 0) wacc[t >> 5] = acc;
        __syncthreads();
        if (t == 0) {
            unsigned a = 0;
#pragma unroll
            for (int i = 0; i < 8; i++) a |= wacc[i];
            s_is64 = (a == 0);
        }
        __syncthreads();
        bool is64 = s_is64;
#pragma unroll
        for (int i = 0; i < 8; i++) {
            int e = base + t + 256 * i;
            if (e < N_EDGES) {
                int s, d;
                if (is64) {
                    const long long* q = (const long long*)p;
                    s = (int)q[e]; d = (int)q[N_EDGES + e];
                } else {
                    const int* q = (const int*)p;
                    s = q[e]; d = q[N_EDGES + e];
                }
                g_src[e] = s;
                g_dst[e] = d;
                atomicAdd(&g_cnt[d], 1);
            }
        }
    } else {
        int wb = b - PREP_BLOCKS;
        if (wb < 64) {
            int j = wb * 256 + t;           // j = n*64 + k
            int n = j >> 6, k = j & 63;
            g_WhT[j] = __float2half(W[k * 256 + n]);
        } else if (t < 192) {
            int pair = t >> 4, l = t & 15;  // pair = d*4 + h
            int d = pair >> 2, hh = pair & 3;
            float s = 0.0f;
#pragma unroll
            for (int q = 0; q < 4; q++)
                s += W_edge[d * 256 + hh * 64 + l + 16 * q] * att_edge[hh * 64 + l + 16 * q];
            s += __shfl_xor_sync(0xffffffffu, s, 8);
            s += __shfl_xor_sync(0xffffffffu, s, 4);
            s += __shfl_xor_sync(0xffffffffu, s, 2);
            s += __shfl_xor_sync(0xffffffffu, s, 1);
            if (l == 0) g_v[pair] = s;
        }
    }
}

// ================= K2: local scan blocks + tensor-core GEMM blocks =================
__device__ __forceinline__ void mma16816(float* c, unsigned a0, unsigned a1, unsigned a2,
                                         unsigned a3, unsigned b0, unsigned b1) {
    asm volatile(
        "mma.sync.aligned.m16n8k16.row.col.f32.f16.f16.f32 "
        "{%0,%1,%2,%3},{%4,%5,%6,%7},{%8,%9},{%0,%1,%2,%3};\n"
        : "+f"(c[0]), "+f"(c[1]), "+f"(c[2]), "+f"(c[3])
        : "r"(a0), "r"(a1), "r"(a2), "r"(a3), "r"(b0), "r"(b1));
}

__global__ void __launch_bounds__(256) k_scan_gemm(const float* __restrict__ h,
                                                   const float* __restrict__ att_src,
                                                   const float* __restrict__ att_dst) {
    int t = threadIdx.x;
    if (blockIdx.x < SCAN_BLOCKS) {
        __shared__ int sh[256];
        int b = blockIdx.x;
        int i = b * 256 + t;
        int v = (i < N_NODES) ? g_cnt[i] : 0;
        sh[t] = v;
        __syncthreads();
        for (int off = 1; off < 256; off <<= 1) {
            int u = (t >= off) ? sh[t - off] : 0;
            __syncthreads();
            sh[t] += u;
            __syncthreads();
        }
        g_scan[i] = sh[t];
        if (t == 255) g_btot[b] = sh[255];
        return;
    }
    // ---- GEMM part ----
    __shared__ __half As[32 * 72];
    __shared__ __half Ws[256 * 72];
    int lane = t & 31, w = t >> 5;
    int n0 = (blockIdx.x - SCAN_BLOCKS) * 32;

#pragma unroll
    for (int q = 0; q < 8; q++) {
        int j = t + 256 * q;
        int n = j >> 3, c = j & 7;
        *(uint4*)&Ws[n * 72 + c * 8] = ((const uint4*)g_WhT)[j];
    }
#pragma unroll
    for (int q = 0; q < 2; q++) {
        int i = t + 256 * q;
        int r = i >> 4, c4 = (i & 15) * 4;
        int node = n0 + r;
        float4 hv = (node < N_NODES) ? *(const float4*)&h[node * 64 + c4]
                                     : make_float4(0.f, 0.f, 0.f, 0.f);
        __half2 p0 = __floats2half2_rn(hv.x, hv.y);
        __half2 p1 = __floats2half2_rn(hv.z, hv.w);
        uint2 pk = {*(unsigned*)&p0, *(unsigned*)&p1};
        *(uint2*)&As[r * 72 + c4] = pk;
    }
    __syncthreads();

    int rt = w & 1, cg = w >> 1;
    int rbase = rt * 16;
    int qr = lane >> 2, qc = lane & 3;

    float acc[8][4];
#pragma unroll
    for (int i = 0; i < 8; i++)
#pragma unroll
        for (int j = 0; j < 4; j++) acc[i][j] = 0.f;

#pragma unroll
    for (int ks = 0; ks < 4; ks++) {
        int kk = ks * 16;
        unsigned a0 = *(const unsigned*)&As[(rbase + qr) * 72 + kk + 2 * qc];
        unsigned a1 = *(const unsigned*)&As[(rbase + qr + 8) * 72 + kk + 2 * qc];
        unsigned a2 = *(const unsigned*)&As[(rbase + qr) * 72 + kk + 8 + 2 * qc];
        unsigned a3 = *(const unsigned*)&As[(rbase + qr + 8) * 72 + kk + 8 + 2 * qc];
#pragma unroll
        for (int nf = 0; nf < 8; nf++) {
            int n = cg * 64 + nf * 8 + qr;
            unsigned b0 = *(const unsigned*)&Ws[n * 72 + kk + 2 * qc];
            unsigned b1 = *(const unsigned*)&Ws[n * 72 + kk + 8 + 2 * qc];
            mma16816(acc[nf], a0, a1, a2, a3, b0, b1);
        }
    }

    int node_lo = n0 + rbase + qr;
    int node_hi = node_lo + 8;
    float ps_lo = 0.f, ps_hi = 0.f, pd_lo = 0.f, pd_hi = 0.f;
#pragma unroll
    for (int nf = 0; nf < 8; nf++) {
        int col = cg * 64 + nf * 8 + 2 * qc;
        float2 sv = *(const float2*)&att_src[col];
        float2 dv = *(const float2*)&att_dst[col];
        ps_lo += acc[nf][0] * sv.x + acc[nf][1] * sv.y;
        ps_hi += acc[nf][2] * sv.x + acc[nf][3] * sv.y;
        pd_lo += acc[nf][0] * dv.x + acc[nf][1] * dv.y;
        pd_hi += acc[nf][2] * dv.x + acc[nf][3] * dv.y;
        if (node_lo < N_NODES)
            g_x2[node_lo * 128 + cg * 32 + nf * 4 + qc] = __floats2half2_rn(acc[nf][0], acc[nf][1]);
        if (node_hi < N_NODES)
            g_x2[node_hi * 128 + cg * 32 + nf * 4 + qc] = __floats2half2_rn(acc[nf][2], acc[nf][3]);
    }
    ps_lo += __shfl_xor_sync(0xffffffffu, ps_lo, 1);
    ps_lo += __shfl_xor_sync(0xffffffffu, ps_lo, 2);
    ps_hi += __shfl_xor_sync(0xffffffffu, ps_hi, 1);
    ps_hi += __shfl_xor_sync(0xffffffffu, ps_hi, 2);
    pd_lo += __shfl_xor_sync(0xffffffffu, pd_lo, 1);
    pd_lo += __shfl_xor_sync(0xffffffffu, pd_lo, 2);
    pd_hi += __shfl_xor_sync(0xffffffffu, pd_hi, 1);
    pd_hi += __shfl_xor_sync(0xffffffffu, pd_hi, 2);
    if (qc == 0) {
        if (node_lo < N_NODES) { g_asrc[node_lo * 4 + cg] = ps_lo; g_adst[node_lo * 4 + cg] = pd_lo; }
        if (node_hi < N_NODES) { g_asrc[node_hi * 4 + cg] = ps_hi; g_adst[node_hi * 4 + cg] = pd_hi; }
    }
}

// ================= K3: scanB — block offsets, write off/cur, reset cnt =================
__global__ void __launch_bounds__(256) k_scanB() {
    __shared__ int wsum[8];
    int b = blockIdx.x, t = threadIdx.x;
    int v = (t < SCAN_BLOCKS && t < b) ? g_btot[t] : 0;
#pragma unroll
    for (int o = 16; o; o >>= 1) v += __shfl_xor_sync(0xffffffffu, v, o);
    if ((t & 31) == 0) wsum[t >> 5] = v;
    __syncthreads();
    int boff = 0;
#pragma unroll
    for (int i = 0; i < 8; i++) boff += wsum[i];
    int i = b * 256 + t;
    if (i < N_NODES) {
        int c = g_cnt[i];
        int off = g_scan[i] - c + boff;   // exclusive prefix
        g_off[i] = off;
        g_cur[i] = off;
        g_cnt[i] = 0;                     // invariant: cnt==0 at start of next replay
    }
    if (b == 0 && t == 0) g_off[N_NODES] = N_EDGES;
}

// ================= K4: scatter — sorted {partial alpha, src} per dst =================
__global__ void k_scatter(const float* __restrict__ attr) {
    int e = blockIdx.x * blockDim.x + threadIdx.x;
    if (e >= N_EDGES) return;
    int s = g_src[e], d = g_dst[e];
    float a0 = attr[e * 3 + 0], a1 = attr[e * 3 + 1], a2 = attr[e * 3 + 2];
    float4 as = *(const float4*)&g_asrc[s * 4];
    float4 outv;
    outv.x = as.x + a0 * g_v[0] + a1 * g_v[4] + a2 * g_v[8];
    outv.y = as.y + a0 * g_v[1] + a1 * g_v[5] + a2 * g_v[9];
    outv.z = as.z + a0 * g_v[2] + a1 * g_v[6] + a2 * g_v[10];
    outv.w = as.w + a0 * g_v[3] + a1 * g_v[7] + a2 * g_v[11];
    int pos = atomicAdd(&g_cur[d], 1);
    *(float4*)&g_salpha[pos * 4] = outv;
    g_ssrc[pos] = s;
}

// ================= K5: warp per node — online softmax + fp16 gather + LN + SiLU =====
__global__ void __launch_bounds__(256) k_node(float* __restrict__ out,
                                              const float* __restrict__ bias,
                                              const float* __restrict__ gamma,
                                              const float* __restrict__ beta) {
    int t = threadIdx.x, lane = t & 31, w = t >> 5;
    int n = blockIdx.x * 8 + w;
    int beg = g_off[n], end = g_off[n + 1];
    const float4* sal = (const float4*)g_salpha;
    float4 ad = *(const float4*)&g_adst[n * 4];

    // merged max+sumexp (online)
    const float NINF = __int_as_float(0xff800000);
    float4 m = {NINF, NINF, NINF, NINF};
    float4 s = {0.f, 0.f, 0.f, 0.f};
    for (int k = beg + lane; k < end; k += 32) {
        float4 a = sal[k];
        a.x += ad.x; a.y += ad.y; a.z += ad.z; a.w += ad.w;
        a.x = a.x > 0.f ? a.x : 0.2f * a.x;
        a.y = a.y > 0.f ? a.y : 0.2f * a.y;
        a.z = a.z > 0.f ? a.z : 0.2f * a.z;
        a.w = a.w > 0.f ? a.w : 0.2f * a.w;
        float nm;
        nm = fmaxf(m.x, a.x); s.x = s.x * expf(m.x - nm) + expf(a.x - nm); m.x = nm;
        nm = fmaxf(m.y, a.y); s.y = s.y * expf(m.y - nm) + expf(a.y - nm); m.y = nm;
        nm = fmaxf(m.z, a.z); s.z = s.z * expf(m.z - nm) + expf(a.z - nm); m.z = nm;
        nm = fmaxf(m.w, a.w); s.w = s.w * expf(m.w - nm) + expf(a.w - nm); m.w = nm;
    }
#pragma unroll
    for (int o = 16; o; o >>= 1) {
        float om, os, nm, scm, sco;
        om = __shfl_xor_sync(0xffffffffu, m.x, o); os = __shfl_xor_sync(0xffffffffu, s.x, o);
        nm = fmaxf(m.x, om);
        scm = (m.x == nm) ? 1.f : expf(m.x - nm);
        sco = (om == nm) ? 1.f : expf(om - nm);
        s.x = s.x * scm + os * sco; m.x = nm;
        om = __shfl_xor_sync(0xffffffffu, m.y, o); os = __shfl_xor_sync(0xffffffffu, s.y, o);
        nm = fmaxf(m.y, om);
        scm = (m.y == nm) ? 1.f : expf(m.y - nm);
        sco = (om == nm) ? 1.f : expf(om - nm);
        s.y = s.y * scm + os * sco; m.y = nm;
        om = __shfl_xor_sync(0xffffffffu, m.z, o); os = __shfl_xor_sync(0xffffffffu, s.z, o);
        nm = fmaxf(m.z, om);
        scm = (m.z == nm) ? 1.f : expf(m.z - nm);
        sco = (om == nm) ? 1.f : expf(om - nm);
        s.z = s.z * scm + os * sco; m.z = nm;
        om = __shfl_xor_sync(0xffffffffu, m.w, o); os = __shfl_xor_sync(0xffffffffu, s.w, o);
        nm = fmaxf(m.w, om);
        scm = (m.w == nm) ? 1.f : expf(m.w - nm);
        sco = (om == nm) ? 1.f : expf(om - nm);
        s.w = s.w * scm + os * sco; m.w = nm;
    }

    // per-lane head constants
    int hd = lane >> 3;
    float mh  = (hd == 0) ? m.x : (hd == 1) ? m.y : (hd == 2) ? m.z : m.w;
    float sh_ = (hd == 0) ? s.x : (hd == 1) ? s.y : (hd == 2) ? s.z : s.w;
    float adh = (hd == 0) ? ad.x : (hd == 1) ? ad.y : (hd == 2) ? ad.z : ad.w;
    float ih = 0.25f / (sh_ + 1e-16f);

    // pass 3: weighted fp16 gather, unrolled x2
    float acc[8];
#pragma unroll
    for (int i = 0; i < 8; i++) acc[i] = 0.f;
    const uint4* xv4 = (const uint4*)g_x2;
    int k = beg;
    for (; k + 2 <= end; k += 2) {
        float4 A0 = sal[k], A1 = sal[k + 1];
        int s0 = g_ssrc[k], s1 = g_ssrc[k + 1];
        uint4 X0 = xv4[s0 * 32 + lane];
        uint4 X1 = xv4[s1 * 32 + lane];
        float a0 = ((hd == 0) ? A0.x : (hd == 1) ? A0.y : (hd == 2) ? A0.z : A0.w) + adh;
        float a1 = ((hd == 0) ? A1.x : (hd == 1) ? A1.y : (hd == 2) ? A1.z : A1.w) + adh;
        a0 = a0 > 0.f ? a0 : 0.2f * a0;
        a1 = a1 > 0.f ? a1 : 0.2f * a1;
        float w0 = expf(a0 - mh) * ih;
        float w1 = expf(a1 - mh) * ih;
        const __half2* h0 = (const __half2*)&X0;
        const __half2* h1 = (const __half2*)&X1;
#pragma unroll
        for (int i = 0; i < 4; i++) {
            float2 f0 = __half22float2(h0[i]);
            float2 f1 = __half22float2(h1[i]);
            acc[2 * i]     += w0 * f0.x + w1 * f1.x;
            acc[2 * i + 1] += w0 * f0.y + w1 * f1.y;
        }
    }
    if (k < end) {
        float4 A0 = sal[k];
        int s0 = g_ssrc[k];
        uint4 X0 = xv4[s0 * 32 + lane];
        float a0 = ((hd == 0) ? A0.x : (hd == 1) ? A0.y : (hd == 2) ? A0.z : A0.w) + adh;
        a0 = a0 > 0.f ? a0 : 0.2f * a0;
        float w0 = expf(a0 - mh) * ih;
        const __half2* h0 = (const __half2*)&X0;
#pragma unroll
        for (int i = 0; i < 4; i++) {
            float2 f0 = __half22float2(h0[i]);
            acc[2 * i]     += w0 * f0.x;
            acc[2 * i + 1] += w0 * f0.y;
        }
    }
    // fold the 4 head groups
#pragma unroll
    for (int i = 0; i < 8; i++) {
        acc[i] += __shfl_xor_sync(0xffffffffu, acc[i], 8);
        acc[i] += __shfl_xor_sync(0xffffffffu, acc[i], 16);
    }

    // LN + SiLU over 64 channels (lanes 0..7 write)
    int j = lane & 7;
    float4 b0 = ((const float4*)bias)[2 * j];
    float4 b1 = ((const float4*)bias)[2 * j + 1];
    float v[8] = {acc[0] + b0.x, acc[1] + b0.y, acc[2] + b0.z, acc[3] + b0.w,
                  acc[4] + b1.x, acc[5] + b1.y, acc[6] + b1.z, acc[7] + b1.w};
    float sum = 0.f, sq = 0.f;
#pragma unroll
    for (int i = 0; i < 8; i++) { sum += v[i]; sq += v[i] * v[i]; }
#pragma unroll
    for (int o = 4; o; o >>= 1) {
        sum += __shfl_xor_sync(0xffffffffu, sum, o);
        sq  += __shfl_xor_sync(0xffffffffu, sq, o);
    }
    float mu  = sum * (1.0f / 64.0f);
    float var = sq * (1.0f / 64.0f) - mu * mu;
    float inv = rsqrtf(var + 1e-5f);
    float4 g0 = ((const float4*)gamma)[2 * j];
    float4 g1 = ((const float4*)gamma)[2 * j + 1];
    float4 e0 = ((const float4*)beta)[2 * j];
    float4 e1 = ((const float4*)beta)[2 * j + 1];
    float gg[8] = {g0.x, g0.y, g0.z, g0.w, g1.x, g1.y, g1.z, g1.w};
    float ee[8] = {e0.x, e0.y, e0.z, e0.w, e1.x, e1.y, e1.z, e1.w};
    float y[8];
#pragma unroll
    for (int i = 0; i < 8; i++) {
        float yy = (v[i] - mu) * inv * gg[i] + ee[i];
        y[i] = yy / (1.0f + expf(-yy));
    }
    if (lane < 8) {
        float4 o0 = {y[0], y[1], y[2], y[3]};
        float4 o1 = {y[4], y[5], y[6], y[7]};
        ((float4*)out)[n * 16 + 2 * j]     = o0;
        ((float4*)out)[n * 16 + 2 * j + 1] = o1;
    }
}

extern "C" void kernel_launch(void* const* d_in, const int* in_sizes, int n_in,
                              void* d_out, int out_size) {
    // order: t, h, edge_index, edge_attr, W, att_src, att_dst,
    //        W_edge, att_edge, bias, ln_gamma, ln_beta
    const float* h        = (const float*)d_in[1];
    const void*  ei       = d_in[2];
    const float* attr     = (const float*)d_in[3];
    const float* W        = (const float*)d_in[4];
    const float* att_src  = (const float*)d_in[5];
    const float* att_dst  = (const float*)d_in[6];
    const float* W_edge   = (const float*)d_in[7];
    const float* att_edge = (const float*)d_in[8];
    const float* bias     = (const float*)d_in[9];
    const float* gamma    = (const float*)d_in[10];
    const float* beta     = (const float*)d_in[11];
    float* out = (float*)d_out;

    k_prep_wconv<<<PREP_BLOCKS + 65, 256>>>((const unsigned*)ei, W, W_edge, att_edge);
    k_scan_gemm <<<SCAN_BLOCKS + GEMM_BLOCKS, 256>>>(h, att_src, att_dst);
    k_scanB     <<<SCAN_BLOCKS, 256>>>();
    k_scatter   <<<(N_EDGES + 255) / 256, 256>>>(attr);
    k_node      <<<N_NODES / 8, 256>>>(out, bias, gamma, beta);
}

// round 5
// speedup vs baseline: 1.1125x; 1.1125x over previous
#include <cuda_runtime.h>
#include <cuda_fp16.h>

#define N_NODES 50000
#define N_EDGES 800000
#define NB_SCAN 49          // ceil(50000/1024)

// ---------------- scratch (static device globals; no allocation) ----------------
__device__ int   g_is64;
__device__ __align__(16) int   g_src[N_EDGES];
__device__ __align__(16) int   g_dst[N_EDGES];
__device__ __align__(16) int   g_rank[N_EDGES];
__device__ int   g_cnt[N_NODES];
__device__ int   g_scan[NB_SCAN * 1024];
__device__ int   g_btot[NB_SCAN];
__device__ int   g_off[N_NODES + 1];
__device__ __align__(16) int     g_ssrc[N_EDGES];
__device__ __align__(16) float   g_salpha[N_EDGES * 4];    // full leaky logits, 12.8 MB
__device__ __align__(16) __half2 g_x2[N_NODES * 128];      // x in fp16, 25.6 MB
__device__ __align__(16) float   g_asrc[N_NODES * 4];
__device__ __align__(16) float   g_adst[N_NODES * 4];
__device__ __align__(16) __half  g_WhT[256 * 64];          // W transposed [n][k], fp16
__device__ float g_v[12];                                  // [edim*4 + head]

// ---------------- init: zero histogram + dtype sniffer ----------------
__global__ void k_init(const unsigned* __restrict__ p) {
    if (blockIdx.x < 196) {
        int i = blockIdx.x * 256 + threadIdx.x;
        if (i < N_NODES) g_cnt[i] = 0;
        if (blockIdx.x == 0 && threadIdx.x == 0) g_off[N_NODES] = N_EDGES;
    } else {
        __shared__ int bad;
        if (threadIdx.x == 0) bad = 0;
        __syncthreads();
        unsigned acc = 0;
#pragma unroll
        for (int i = 0; i < 4; i++) acc |= p[2 * (threadIdx.x * 4 + i) + 1];
        if (acc) atomicOr(&bad, 1);
        __syncthreads();
        if (threadIdx.x == 0) g_is64 = bad ? 0 : 1;
    }
}

// ---------------- unpack edge_index + dst histogram (rank captured) ----------------
__global__ void k_prep(const void* __restrict__ p) {
    int e = blockIdx.x * blockDim.x + threadIdx.x;
    if (e >= N_EDGES) return;
    int s, d;
    if (g_is64) {
        const long long* q = (const long long*)p;
        s = (int)q[e]; d = (int)q[N_EDGES + e];
    } else {
        const int* q = (const int*)p;
        s = q[e]; d = q[N_EDGES + e];
    }
    g_src[e] = s;
    g_dst[e] = d;
    g_rank[e] = atomicAdd(&g_cnt[d], 1);
}

// ---------------- scan part 1: per-block inclusive scan ----------------
__global__ void k_scan1() {
    __shared__ int s[1024];
    int b = blockIdx.x, t = threadIdx.x;
    int i = b * 1024 + t;
    int v = (i < N_NODES) ? g_cnt[i] : 0;
    s[t] = v;
    __syncthreads();
    for (int off = 1; off < 1024; off <<= 1) {
        int u = (t >= off) ? s[t - off] : 0;
        __syncthreads();
        s[t] += u;
        __syncthreads();
    }
    g_scan[i] = s[t];
    if (t == 1023) g_btot[b] = s[t];
}

// ---------------- scan part 2: block offsets + write g_off ----------------
__global__ void k_scanB() {
    __shared__ int wsum[2];
    int b = blockIdx.x, t = threadIdx.x;
    // block offset = sum of btot[0..b-1]; threads 0..63 participate
    int v = (t < NB_SCAN && t < b) ? g_btot[t] : 0;
    if (t < 64) {
#pragma unroll
        for (int o = 16; o; o >>= 1) v += __shfl_xor_sync(0xffffffffu, v, o);
        if ((t & 31) == 0) wsum[t >> 5] = v;
    }
    __syncthreads();
    int boff = wsum[0] + wsum[1];
    int i = b * 1024 + t;
    if (i < N_NODES)
        g_off[i] = g_scan[i] - g_cnt[i] + boff;   // exclusive prefix
}

// ---------------- W transpose->fp16, plus v_edge reduction ----------------
__global__ void k_wconv(const float* __restrict__ W, const float* __restrict__ W_edge,
                        const float* __restrict__ att_edge) {
    if (blockIdx.x < 64) {
        int j = blockIdx.x * 256 + threadIdx.x;   // j = n*64 + k
        int n = j >> 6, k = j & 63;
        g_WhT[j] = __float2half(W[k * 256 + n]);
    } else {
        int t = threadIdx.x;
        if (t < 192) {
            int pair = t >> 4, l = t & 15;        // pair = d*4 + h
            int d = pair >> 2, hh = pair & 3;
            float s = 0.0f;
#pragma unroll
            for (int q = 0; q < 4; q++)
                s += W_edge[d * 256 + hh * 64 + l + 16 * q] * att_edge[hh * 64 + l + 16 * q];
            s += __shfl_xor_sync(0xffffffffu, s, 8);
            s += __shfl_xor_sync(0xffffffffu, s, 4);
            s += __shfl_xor_sync(0xffffffffu, s, 2);
            s += __shfl_xor_sync(0xffffffffu, s, 1);
            if (l == 0) g_v[pair] = s;
        }
    }
}

// ---------------- tensor-core GEMM x = h @ W, fused a_src/a_dst ----------------
__device__ __forceinline__ void mma16816(float* c, unsigned a0, unsigned a1, unsigned a2,
                                         unsigned a3, unsigned b0, unsigned b1) {
    asm volatile(
        "mma.sync.aligned.m16n8k16.row.col.f32.f16.f16.f32 "
        "{%0,%1,%2,%3},{%4,%5,%6,%7},{%8,%9},{%0,%1,%2,%3};\n"
        : "+f"(c[0]), "+f"(c[1]), "+f"(c[2]), "+f"(c[3])
        : "r"(a0), "r"(a1), "r"(a2), "r"(a3), "r"(b0), "r"(b1));
}

__global__ void __launch_bounds__(256) k_gemm(const float* __restrict__ h,
                                              const float* __restrict__ att_src,
                                              const float* __restrict__ att_dst) {
    __shared__ __half As[32 * 72];
    __shared__ __half Ws[256 * 72];
    int t = threadIdx.x, lane = t & 31, w = t >> 5;
    int n0 = blockIdx.x * 32;

#pragma unroll
    for (int q = 0; q < 8; q++) {
        int j = t + 256 * q;
        int n = j >> 3, c = j & 7;
        *(uint4*)&Ws[n * 72 + c * 8] = ((const uint4*)g_WhT)[j];
    }
#pragma unroll
    for (int q = 0; q < 2; q++) {
        int i = t + 256 * q;
        int r = i >> 4, c4 = (i & 15) * 4;
        int node = n0 + r;
        float4 hv = (node < N_NODES) ? *(const float4*)&h[node * 64 + c4]
                                     : make_float4(0.f, 0.f, 0.f, 0.f);
        __half2 p0 = __floats2half2_rn(hv.x, hv.y);
        __half2 p1 = __floats2half2_rn(hv.z, hv.w);
        uint2 pk = {*(unsigned*)&p0, *(unsigned*)&p1};
        *(uint2*)&As[r * 72 + c4] = pk;
    }
    __syncthreads();

    int rt = w & 1, cg = w >> 1;
    int rbase = rt * 16;
    int qr = lane >> 2, qc = lane & 3;

    float acc[8][4];
#pragma unroll
    for (int i = 0; i < 8; i++)
#pragma unroll
        for (int j = 0; j < 4; j++) acc[i][j] = 0.f;

#pragma unroll
    for (int ks = 0; ks < 4; ks++) {
        int kk = ks * 16;
        unsigned a0 = *(const unsigned*)&As[(rbase + qr) * 72 + kk + 2 * qc];
        unsigned a1 = *(const unsigned*)&As[(rbase + qr + 8) * 72 + kk + 2 * qc];
        unsigned a2 = *(const unsigned*)&As[(rbase + qr) * 72 + kk + 8 + 2 * qc];
        unsigned a3 = *(const unsigned*)&As[(rbase + qr + 8) * 72 + kk + 8 + 2 * qc];
#pragma unroll
        for (int nf = 0; nf < 8; nf++) {
            int n = cg * 64 + nf * 8 + qr;
            unsigned b0 = *(const unsigned*)&Ws[n * 72 + kk + 2 * qc];
            unsigned b1 = *(const unsigned*)&Ws[n * 72 + kk + 8 + 2 * qc];
            mma16816(acc[nf], a0, a1, a2, a3, b0, b1);
        }
    }

    int node_lo = n0 + rbase + qr;
    int node_hi = node_lo + 8;
    float ps_lo = 0.f, ps_hi = 0.f, pd_lo = 0.f, pd_hi = 0.f;
#pragma unroll
    for (int nf = 0; nf < 8; nf++) {
        int col = cg * 64 + nf * 8 + 2 * qc;
        float2 sv = *(const float2*)&att_src[col];
        float2 dv = *(const float2*)&att_dst[col];
        ps_lo += acc[nf][0] * sv.x + acc[nf][1] * sv.y;
        ps_hi += acc[nf][2] * sv.x + acc[nf][3] * sv.y;
        pd_lo += acc[nf][0] * dv.x + acc[nf][1] * dv.y;
        pd_hi += acc[nf][2] * dv.x + acc[nf][3] * dv.y;
        if (node_lo < N_NODES)
            g_x2[node_lo * 128 + cg * 32 + nf * 4 + qc] = __floats2half2_rn(acc[nf][0], acc[nf][1]);
        if (node_hi < N_NODES)
            g_x2[node_hi * 128 + cg * 32 + nf * 4 + qc] = __floats2half2_rn(acc[nf][2], acc[nf][3]);
    }
    ps_lo += __shfl_xor_sync(0xffffffffu, ps_lo, 1);
    ps_lo += __shfl_xor_sync(0xffffffffu, ps_lo, 2);
    ps_hi += __shfl_xor_sync(0xffffffffu, ps_hi, 1);
    ps_hi += __shfl_xor_sync(0xffffffffu, ps_hi, 2);
    pd_lo += __shfl_xor_sync(0xffffffffu, pd_lo, 1);
    pd_lo += __shfl_xor_sync(0xffffffffu, pd_lo, 2);
    pd_hi += __shfl_xor_sync(0xffffffffu, pd_hi, 1);
    pd_hi += __shfl_xor_sync(0xffffffffu, pd_hi, 2);
    if (qc == 0) {
        if (node_lo < N_NODES) { g_asrc[node_lo * 4 + cg] = ps_lo; g_adst[node_lo * 4 + cg] = pd_lo; }
        if (node_hi < N_NODES) { g_asrc[node_hi * 4 + cg] = ps_hi; g_adst[node_hi * 4 + cg] = pd_hi; }
    }
}

// ---------------- scatter: atomic-free, 4 edges/thread, smem-staged attr ----------------
__global__ void __launch_bounds__(256) k_scatter(const float* __restrict__ attr) {
    __shared__ float sattr[3072];   // 1024 edges * 3 floats
    int t = threadIdx.x;
    int base = blockIdx.x * 1024;
    // coalesced stage of edge_attr for this block's 1024 edges
    int navail = N_EDGES - base; if (navail > 1024) navail = 1024;
    int nflt = navail * 3;
#pragma unroll
    for (int q = 0; q < 12; q++) {
        int i = t + 256 * q;
        if (i < nflt) sattr[i] = attr[base * 3 + i];
    }
    __syncthreads();

    float v0x = g_v[0], v0y = g_v[1], v0z = g_v[2], v0w = g_v[3];
    float v1x = g_v[4], v1y = g_v[5], v1z = g_v[6], v1w = g_v[7];
    float v2x = g_v[8], v2y = g_v[9], v2z = g_v[10], v2w = g_v[11];

#pragma unroll
    for (int q = 0; q < 4; q++) {
        int le = t + 256 * q;
        int e = base + le;
        if (e >= N_EDGES) break;
        int s = g_src[e], d = g_dst[e], r = g_rank[e];
        int pos = g_off[d] + r;
        float a0 = sattr[le * 3 + 0], a1 = sattr[le * 3 + 1], a2 = sattr[le * 3 + 2];
        float4 as = *(const float4*)&g_asrc[s * 4];
        float4 ad = *(const float4*)&g_adst[d * 4];
        float4 o;
        o.x = as.x + ad.x + a0 * v0x + a1 * v1x + a2 * v2x;
        o.y = as.y + ad.y + a0 * v0y + a1 * v1y + a2 * v2y;
        o.z = as.z + ad.z + a0 * v0z + a1 * v1z + a2 * v2z;
        o.w = as.w + ad.w + a0 * v0w + a1 * v1w + a2 * v2w;
        o.x = o.x > 0.f ? o.x : 0.2f * o.x;
        o.y = o.y > 0.f ? o.y : 0.2f * o.y;
        o.z = o.z > 0.f ? o.z : 0.2f * o.z;
        o.w = o.w > 0.f ? o.w : 0.2f * o.w;
        *(float4*)&g_salpha[pos * 4] = o;
        g_ssrc[pos] = s;
    }
}

// ---------------- warp per node: softmax + fp16 gather + LN + SiLU ----------------
__global__ void __launch_bounds__(256) k_node(float* __restrict__ out,
                                              const float* __restrict__ bias,
                                              const float* __restrict__ gamma,
                                              const float* __restrict__ beta) {
    int t = threadIdx.x, lane = t & 31, w = t >> 5;
    int n = blockIdx.x * 8 + w;
    int beg = g_off[n], end = g_off[n + 1];
    const float4* sal = (const float4*)g_salpha;

    // pass 1: segment max per head
    const float NINF = __int_as_float(0xff800000);
    float4 m = {NINF, NINF, NINF, NINF};
    for (int k = beg + lane; k < end; k += 32) {
        float4 a = sal[k];
        m.x = fmaxf(m.x, a.x); m.y = fmaxf(m.y, a.y);
        m.z = fmaxf(m.z, a.z); m.w = fmaxf(m.w, a.w);
    }
#pragma unroll
    for (int o = 16; o; o >>= 1) {
        m.x = fmaxf(m.x, __shfl_xor_sync(0xffffffffu, m.x, o));
        m.y = fmaxf(m.y, __shfl_xor_sync(0xffffffffu, m.y, o));
        m.z = fmaxf(m.z, __shfl_xor_sync(0xffffffffu, m.z, o));
        m.w = fmaxf(m.w, __shfl_xor_sync(0xffffffffu, m.w, o));
    }

    // pass 2: sum of exp
    float4 sm = {0.f, 0.f, 0.f, 0.f};
    for (int k = beg + lane; k < end; k += 32) {
        float4 a = sal[k];
        sm.x += expf(a.x - m.x); sm.y += expf(a.y - m.y);
        sm.z += expf(a.z - m.z); sm.w += expf(a.w - m.w);
    }
#pragma unroll
    for (int o = 16; o; o >>= 1) {
        sm.x += __shfl_xor_sync(0xffffffffu, sm.x, o);
        sm.y += __shfl_xor_sync(0xffffffffu, sm.y, o);
        sm.z += __shfl_xor_sync(0xffffffffu, sm.z, o);
        sm.w += __shfl_xor_sync(0xffffffffu, sm.w, o);
    }

    // per-lane head constants
    int hd = lane >> 3;
    float mh = (hd == 0) ? m.x : (hd == 1) ? m.y : (hd == 2) ? m.z : m.w;
    float sh = (hd == 0) ? sm.x : (hd == 1) ? sm.y : (hd == 2) ? sm.z : sm.w;
    float ih = 0.25f / (sh + 1e-16f);

    // pass 3: weighted gather of fp16 x
    float acc[8];
#pragma unroll
    for (int i = 0; i < 8; i++) acc[i] = 0.f;
    const uint4* xv4 = (const uint4*)g_x2;
    for (int k = beg; k < end; k++) {
        float4 a = sal[k];
        int s = g_ssrc[k];
        float ah = (hd == 0) ? a.x : (hd == 1) ? a.y : (hd == 2) ? a.z : a.w;
        float wgt = expf(ah - mh) * ih;
        uint4 xv = xv4[s * 32 + lane];
        const __half2* hp = (const __half2*)&xv;
#pragma unroll
        for (int i = 0; i < 4; i++) {
            float2 f = __half22float2(hp[i]);
            acc[2 * i]     += wgt * f.x;
            acc[2 * i + 1] += wgt * f.y;
        }
    }
#pragma unroll
    for (int i = 0; i < 8; i++) {
        acc[i] += __shfl_xor_sync(0xffffffffu, acc[i], 8);
        acc[i] += __shfl_xor_sync(0xffffffffu, acc[i], 16);
    }

    // LN + SiLU over 64 channels (lanes 0..7 write)
    int j = lane & 7;
    float4 b0 = ((const float4*)bias)[2 * j];
    float4 b1 = ((const float4*)bias)[2 * j + 1];
    float v[8] = {acc[0] + b0.x, acc[1] + b0.y, acc[2] + b0.z, acc[3] + b0.w,
                  acc[4] + b1.x, acc[5] + b1.y, acc[6] + b1.z, acc[7] + b1.w};
    float sum = 0.f, sq = 0.f;
#pragma unroll
    for (int i = 0; i < 8; i++) { sum += v[i]; sq += v[i] * v[i]; }
#pragma unroll
    for (int o = 4; o; o >>= 1) {
        sum += __shfl_xor_sync(0xffffffffu, sum, o);
        sq  += __shfl_xor_sync(0xffffffffu, sq, o);
    }
    float mu  = sum * (1.0f / 64.0f);
    float var = sq * (1.0f / 64.0f) - mu * mu;
    float inv = rsqrtf(var + 1e-5f);
    float4 g0 = ((const float4*)gamma)[2 * j];
    float4 g1 = ((const float4*)gamma)[2 * j + 1];
    float4 e0 = ((const float4*)beta)[2 * j];
    float4 e1 = ((const float4*)beta)[2 * j + 1];
    float gg[8] = {g0.x, g0.y, g0.z, g0.w, g1.x, g1.y, g1.z, g1.w};
    float ee[8] = {e0.x, e0.y, e0.z, e0.w, e1.x, e1.y, e1.z, e1.w};
    float y[8];
#pragma unroll
    for (int i = 0; i < 8; i++) {
        float yy = (v[i] - mu) * inv * gg[i] + ee[i];
        y[i] = yy / (1.0f + expf(-yy));
    }
    if (lane < 8) {
        float4 o0 = {y[0], y[1], y[2], y[3]};
        float4 o1 = {y[4], y[5], y[6], y[7]};
        ((float4*)out)[n * 16 + 2 * j]     = o0;
        ((float4*)out)[n * 16 + 2 * j + 1] = o1;
    }
}

extern "C" void kernel_launch(void* const* d_in, const int* in_sizes, int n_in,
                              void* d_out, int out_size) {
    // order: t, h, edge_index, edge_attr, W, att_src, att_dst,
    //        W_edge, att_edge, bias, ln_gamma, ln_beta
    const float* h        = (const float*)d_in[1];
    const void*  ei       = d_in[2];
    const float* attr     = (const float*)d_in[3];
    const float* W        = (const float*)d_in[4];
    const float* att_src  = (const float*)d_in[5];
    const float* att_dst  = (const float*)d_in[6];
    const float* W_edge   = (const float*)d_in[7];
    const float* att_edge = (const float*)d_in[8];
    const float* bias     = (const float*)d_in[9];
    const float* gamma    = (const float*)d_in[10];
    const float* beta     = (const float*)d_in[11];
    float* out = (float*)d_out;

    k_init   <<<197, 256>>>((const unsigned*)ei);
    k_prep   <<<(N_EDGES + 255) / 256, 256>>>(ei);
    k_scan1  <<<NB_SCAN, 1024>>>();
    k_scanB  <<<NB_SCAN, 1024>>>();
    k_wconv  <<<65, 256>>>(W, W_edge, att_edge);
    k_gemm   <<<(N_NODES + 31) / 32, 256>>>(h, att_src, att_dst);
    k_scatter<<<(N_EDGES + 1023) / 1024, 256>>>(attr);
    k_node   <<<N_NODES / 8, 256>>>(out, bias, gamma, beta);
}

// round 6
// speedup vs baseline: 1.1636x; 1.0459x over previous
#include <cuda_runtime.h>
#include <cuda_fp16.h>

#define N_NODES 50000
#define N_EDGES 800000
#define NB_SCAN 49          // ceil(50000/1024)

// ---------------- scratch (static device globals; no allocation) ----------------
__device__ int   g_is64;
__device__ __align__(16) int   g_src[N_EDGES];
__device__ __align__(16) int   g_dst[N_EDGES];
__device__ __align__(16) int   g_rank[N_EDGES];
__device__ int   g_cnt[N_NODES];
__device__ int   g_scan[NB_SCAN * 1024];
__device__ int   g_btot[NB_SCAN];
__device__ int   g_off[N_NODES + 1];
__device__ __align__(16) int     g_ssrc[N_EDGES];
__device__ __align__(16) float   g_salpha[N_EDGES * 4];    // full leaky logits, 12.8 MB
__device__ __align__(16) __half2 g_x2[N_NODES * 128];      // x in fp16, 25.6 MB
__device__ __align__(16) float   g_asrc[N_NODES * 4];
__device__ __align__(16) float   g_adst[N_NODES * 4];
__device__ __align__(16) __half  g_WhT[256 * 64];          // W transposed [n][k], fp16
__device__ float g_v[12];                                  // [edim*4 + head]

// ---------------- init: zero histogram + dtype sniffer ----------------
__global__ void k_init(const unsigned* __restrict__ p) {
    if (blockIdx.x < 196) {
        int i = blockIdx.x * 256 + threadIdx.x;
        if (i < N_NODES) g_cnt[i] = 0;
        if (blockIdx.x == 0 && threadIdx.x == 0) g_off[N_NODES] = N_EDGES;
    } else {
        __shared__ int bad;
        if (threadIdx.x == 0) bad = 0;
        __syncthreads();
        unsigned acc = 0;
#pragma unroll
        for (int i = 0; i < 4; i++) acc |= p[2 * (threadIdx.x * 4 + i) + 1];
        if (acc) atomicOr(&bad, 1);
        __syncthreads();
        if (threadIdx.x == 0) g_is64 = bad ? 0 : 1;
    }
}

// ---------------- unpack edge_index + dst histogram (rank captured) ----------------
__global__ void k_prep(const void* __restrict__ p) {
    int e = blockIdx.x * blockDim.x + threadIdx.x;
    if (e >= N_EDGES) return;
    int s, d;
    if (g_is64) {
        const long long* q = (const long long*)p;
        s = (int)q[e]; d = (int)q[N_EDGES + e];
    } else {
        const int* q = (const int*)p;
        s = q[e]; d = q[N_EDGES + e];
    }
    g_src[e] = s;
    g_dst[e] = d;
    g_rank[e] = atomicAdd(&g_cnt[d], 1);
}

// ---------------- scan part 1: per-block inclusive scan ----------------
__global__ void k_scan1() {
    __shared__ int s[1024];
    int b = blockIdx.x, t = threadIdx.x;
    int i = b * 1024 + t;
    int v = (i < N_NODES) ? g_cnt[i] : 0;
    s[t] = v;
    __syncthreads();
    for (int off = 1; off < 1024; off <<= 1) {
        int u = (t >= off) ? s[t - off] : 0;
        __syncthreads();
        s[t] += u;
        __syncthreads();
    }
    g_scan[i] = s[t];
    if (t == 1023) g_btot[b] = s[t];
}

// ---------------- scan part 2: block offsets + write g_off ----------------
__global__ void k_scanB() {
    __shared__ int wsum[2];
    int b = blockIdx.x, t = threadIdx.x;
    int v = (t < NB_SCAN && t < b) ? g_btot[t] : 0;
    if (t < 64) {
#pragma unroll
        for (int o = 16; o; o >>= 1) v += __shfl_xor_sync(0xffffffffu, v, o);
        if ((t & 31) == 0) wsum[t >> 5] = v;
    }
    __syncthreads();
    int boff = wsum[0] + wsum[1];
    int i = b * 1024 + t;
    if (i < N_NODES)
        g_off[i] = g_scan[i] - g_cnt[i] + boff;   // exclusive prefix
}

// ---------------- W transpose->fp16, plus v_edge reduction ----------------
__global__ void k_wconv(const float* __restrict__ W, const float* __restrict__ W_edge,
                        const float* __restrict__ att_edge) {
    if (blockIdx.x < 64) {
        int j = blockIdx.x * 256 + threadIdx.x;   // j = n*64 + k
        int n = j >> 6, k = j & 63;
        g_WhT[j] = __float2half(W[k * 256 + n]);
    } else {
        int t = threadIdx.x;
        if (t < 192) {
            int pair = t >> 4, l = t & 15;        // pair = d*4 + h
            int d = pair >> 2, hh = pair & 3;
            float s = 0.0f;
#pragma unroll
            for (int q = 0; q < 4; q++)
                s += W_edge[d * 256 + hh * 64 + l + 16 * q] * att_edge[hh * 64 + l + 16 * q];
            s += __shfl_xor_sync(0xffffffffu, s, 8);
            s += __shfl_xor_sync(0xffffffffu, s, 4);
            s += __shfl_xor_sync(0xffffffffu, s, 2);
            s += __shfl_xor_sync(0xffffffffu, s, 1);
            if (l == 0) g_v[pair] = s;
        }
    }
}

// ---------------- tensor-core GEMM x = h @ W, fused a_src/a_dst ----------------
__device__ __forceinline__ void mma16816(float* c, unsigned a0, unsigned a1, unsigned a2,
                                         unsigned a3, unsigned b0, unsigned b1) {
    asm volatile(
        "mma.sync.aligned.m16n8k16.row.col.f32.f16.f16.f32 "
        "{%0,%1,%2,%3},{%4,%5,%6,%7},{%8,%9},{%0,%1,%2,%3};\n"
        : "+f"(c[0]), "+f"(c[1]), "+f"(c[2]), "+f"(c[3])
        : "r"(a0), "r"(a1), "r"(a2), "r"(a3), "r"(b0), "r"(b1));
}

__global__ void __launch_bounds__(256) k_gemm(const float* __restrict__ h,
                                              const float* __restrict__ att_src,
                                              const float* __restrict__ att_dst) {
    __shared__ __half As[32 * 72];
    __shared__ __half Ws[256 * 72];
    int t = threadIdx.x, lane = t & 31, w = t >> 5;
    int n0 = blockIdx.x * 32;

#pragma unroll
    for (int q = 0; q < 8; q++) {
        int j = t + 256 * q;
        int n = j >> 3, c = j & 7;
        *(uint4*)&Ws[n * 72 + c * 8] = ((const uint4*)g_WhT)[j];
    }
#pragma unroll
    for (int q = 0; q < 2; q++) {
        int i = t + 256 * q;
        int r = i >> 4, c4 = (i & 15) * 4;
        int node = n0 + r;
        float4 hv = (node < N_NODES) ? *(const float4*)&h[node * 64 + c4]
                                     : make_float4(0.f, 0.f, 0.f, 0.f);
        __half2 p0 = __floats2half2_rn(hv.x, hv.y);
        __half2 p1 = __floats2half2_rn(hv.z, hv.w);
        uint2 pk = {*(unsigned*)&p0, *(unsigned*)&p1};
        *(uint2*)&As[r * 72 + c4] = pk;
    }
    __syncthreads();

    int rt = w & 1, cg = w >> 1;
    int rbase = rt * 16;
    int qr = lane >> 2, qc = lane & 3;

    float acc[8][4];
#pragma unroll
    for (int i = 0; i < 8; i++)
#pragma unroll
        for (int j = 0; j < 4; j++) acc[i][j] = 0.f;

#pragma unroll
    for (int ks = 0; ks < 4; ks++) {
        int kk = ks * 16;
        unsigned a0 = *(const unsigned*)&As[(rbase + qr) * 72 + kk + 2 * qc];
        unsigned a1 = *(const unsigned*)&As[(rbase + qr + 8) * 72 + kk + 2 * qc];
        unsigned a2 = *(const unsigned*)&As[(rbase + qr) * 72 + kk + 8 + 2 * qc];
        unsigned a3 = *(const unsigned*)&As[(rbase + qr + 8) * 72 + kk + 8 + 2 * qc];
#pragma unroll
        for (int nf = 0; nf < 8; nf++) {
            int n = cg * 64 + nf * 8 + qr;
            unsigned b0 = *(const unsigned*)&Ws[n * 72 + kk + 2 * qc];
            unsigned b1 = *(const unsigned*)&Ws[n * 72 + kk + 8 + 2 * qc];
            mma16816(acc[nf], a0, a1, a2, a3, b0, b1);
        }
    }

    int node_lo = n0 + rbase + qr;
    int node_hi = node_lo + 8;
    float ps_lo = 0.f, ps_hi = 0.f, pd_lo = 0.f, pd_hi = 0.f;
#pragma unroll
    for (int nf = 0; nf < 8; nf++) {
        int col = cg * 64 + nf * 8 + 2 * qc;
        float2 sv = *(const float2*)&att_src[col];
        float2 dv = *(const float2*)&att_dst[col];
        ps_lo += acc[nf][0] * sv.x + acc[nf][1] * sv.y;
        ps_hi += acc[nf][2] * sv.x + acc[nf][3] * sv.y;
        pd_lo += acc[nf][0] * dv.x + acc[nf][1] * dv.y;
        pd_hi += acc[nf][2] * dv.x + acc[nf][3] * dv.y;
        if (node_lo < N_NODES)
            g_x2[node_lo * 128 + cg * 32 + nf * 4 + qc] = __floats2half2_rn(acc[nf][0], acc[nf][1]);
        if (node_hi < N_NODES)
            g_x2[node_hi * 128 + cg * 32 + nf * 4 + qc] = __floats2half2_rn(acc[nf][2], acc[nf][3]);
    }
    ps_lo += __shfl_xor_sync(0xffffffffu, ps_lo, 1);
    ps_lo += __shfl_xor_sync(0xffffffffu, ps_lo, 2);
    ps_hi += __shfl_xor_sync(0xffffffffu, ps_hi, 1);
    ps_hi += __shfl_xor_sync(0xffffffffu, ps_hi, 2);
    pd_lo += __shfl_xor_sync(0xffffffffu, pd_lo, 1);
    pd_lo += __shfl_xor_sync(0xffffffffu, pd_lo, 2);
    pd_hi += __shfl_xor_sync(0xffffffffu, pd_hi, 1);
    pd_hi += __shfl_xor_sync(0xffffffffu, pd_hi, 2);
    if (qc == 0) {
        if (node_lo < N_NODES) { g_asrc[node_lo * 4 + cg] = ps_lo; g_adst[node_lo * 4 + cg] = pd_lo; }
        if (node_hi < N_NODES) { g_asrc[node_hi * 4 + cg] = ps_hi; g_adst[node_hi * 4 + cg] = pd_hi; }
    }
}

// ---------------- scatter: 1 edge/thread, atomic-free via precomputed rank ----------------
__global__ void k_scatter(const float* __restrict__ attr) {
    int e = blockIdx.x * blockDim.x + threadIdx.x;
    if (e >= N_EDGES) return;
    int s = g_src[e], d = g_dst[e];
    int pos = g_off[d] + g_rank[e];
    float a0 = attr[e * 3 + 0], a1 = attr[e * 3 + 1], a2 = attr[e * 3 + 2];
    float4 as = *(const float4*)&g_asrc[s * 4];
    float4 ad = *(const float4*)&g_adst[d * 4];
    float4 o;
    o.x = as.x + ad.x + a0 * g_v[0] + a1 * g_v[4] + a2 * g_v[8];
    o.y = as.y + ad.y + a0 * g_v[1] + a1 * g_v[5] + a2 * g_v[9];
    o.z = as.z + ad.z + a0 * g_v[2] + a1 * g_v[6] + a2 * g_v[10];
    o.w = as.w + ad.w + a0 * g_v[3] + a1 * g_v[7] + a2 * g_v[11];
    o.x = o.x > 0.f ? o.x : 0.2f * o.x;
    o.y = o.y > 0.f ? o.y : 0.2f * o.y;
    o.z = o.z > 0.f ? o.z : 0.2f * o.z;
    o.w = o.w > 0.f ? o.w : 0.2f * o.w;
    *(float4*)&g_salpha[pos * 4] = o;
    g_ssrc[pos] = s;
}

// ---------------- warp per node: softmax + fp16 gather + LN + SiLU ----------------
__global__ void __launch_bounds__(256) k_node(float* __restrict__ out,
                                              const float* __restrict__ bias,
                                              const float* __restrict__ gamma,
                                              const float* __restrict__ beta) {
    int t = threadIdx.x, lane = t & 31, w = t >> 5;
    int n = blockIdx.x * 8 + w;
    int beg = g_off[n], end = g_off[n + 1];
    const float4* sal = (const float4*)g_salpha;

    // pass 1: segment max per head
    const float NINF = __int_as_float(0xff800000);
    float4 m = {NINF, NINF, NINF, NINF};
    for (int k = beg + lane; k < end; k += 32) {
        float4 a = sal[k];
        m.x = fmaxf(m.x, a.x); m.y = fmaxf(m.y, a.y);
        m.z = fmaxf(m.z, a.z); m.w = fmaxf(m.w, a.w);
    }
#pragma unroll
    for (int o = 16; o; o >>= 1) {
        m.x = fmaxf(m.x, __shfl_xor_sync(0xffffffffu, m.x, o));
        m.y = fmaxf(m.y, __shfl_xor_sync(0xffffffffu, m.y, o));
        m.z = fmaxf(m.z, __shfl_xor_sync(0xffffffffu, m.z, o));
        m.w = fmaxf(m.w, __shfl_xor_sync(0xffffffffu, m.w, o));
    }

    // pass 2: sum of exp
    float4 sm = {0.f, 0.f, 0.f, 0.f};
    for (int k = beg + lane; k < end; k += 32) {
        float4 a = sal[k];
        sm.x += expf(a.x - m.x); sm.y += expf(a.y - m.y);
        sm.z += expf(a.z - m.z); sm.w += expf(a.w - m.w);
    }
#pragma unroll
    for (int o = 16; o; o >>= 1) {
        sm.x += __shfl_xor_sync(0xffffffffu, sm.x, o);
        sm.y += __shfl_xor_sync(0xffffffffu, sm.y, o);
        sm.z += __shfl_xor_sync(0xffffffffu, sm.z, o);
        sm.w += __shfl_xor_sync(0xffffffffu, sm.w, o);
    }

    // per-lane head constants
    int hd = lane >> 3;
    float mh = (hd == 0) ? m.x : (hd == 1) ? m.y : (hd == 2) ? m.z : m.w;
    float sh = (hd == 0) ? sm.x : (hd == 1) ? sm.y : (hd == 2) ? sm.z : sm.w;
    float ih = 0.25f / (sh + 1e-16f);

    // pass 3: weighted gather of fp16 x
    float acc[8];
#pragma unroll
    for (int i = 0; i < 8; i++) acc[i] = 0.f;
    const uint4* xv4 = (const uint4*)g_x2;
    for (int k = beg; k < end; k++) {
        float4 a = sal[k];
        int s = g_ssrc[k];
        float ah = (hd == 0) ? a.x : (hd == 1) ? a.y : (hd == 2) ? a.z : a.w;
        float wgt = expf(ah - mh) * ih;
        uint4 xv = xv4[s * 32 + lane];
        const __half2* hp = (const __half2*)&xv;
#pragma unroll
        for (int i = 0; i < 4; i++) {
            float2 f = __half22float2(hp[i]);
            acc[2 * i]     += wgt * f.x;
            acc[2 * i + 1] += wgt * f.y;
        }
    }
#pragma unroll
    for (int i = 0; i < 8; i++) {
        acc[i] += __shfl_xor_sync(0xffffffffu, acc[i], 8);
        acc[i] += __shfl_xor_sync(0xffffffffu, acc[i], 16);
    }

    // LN + SiLU over 64 channels (lanes 0..7 write)
    int j = lane & 7;
    float4 b0 = ((const float4*)bias)[2 * j];
    float4 b1 = ((const float4*)bias)[2 * j + 1];
    float v[8] = {acc[0] + b0.x, acc[1] + b0.y, acc[2] + b0.z, acc[3] + b0.w,
                  acc[4] + b1.x, acc[5] + b1.y, acc[6] + b1.z, acc[7] + b1.w};
    float sum = 0.f, sq = 0.f;
#pragma unroll
    for (int i = 0; i < 8; i++) { sum += v[i]; sq += v[i] * v[i]; }
#pragma unroll
    for (int o = 4; o; o >>= 1) {
        sum += __shfl_xor_sync(0xffffffffu, sum, o);
        sq  += __shfl_xor_sync(0xffffffffu, sq, o);
    }
    float mu  = sum * (1.0f / 64.0f);
    float var = sq * (1.0f / 64.0f) - mu * mu;
    float inv = rsqrtf(var + 1e-5f);
    float4 g0 = ((const float4*)gamma)[2 * j];
    float4 g1 = ((const float4*)gamma)[2 * j + 1];
    float4 e0 = ((const float4*)beta)[2 * j];
    float4 e1 = ((const float4*)beta)[2 * j + 1];
    float gg[8] = {g0.x, g0.y, g0.z, g0.w, g1.x, g1.y, g1.z, g1.w};
    float ee[8] = {e0.x, e0.y, e0.z, e0.w, e1.x, e1.y, e1.z, e1.w};
    float y[8];
#pragma unroll
    for (int i = 0; i < 8; i++) {
        float yy = (v[i] - mu) * inv * gg[i] + ee[i];
        y[i] = yy / (1.0f + expf(-yy));
    }
    if (lane < 8) {
        float4 o0 = {y[0], y[1], y[2], y[3]};
        float4 o1 = {y[4], y[5], y[6], y[7]};
        ((float4*)out)[n * 16 + 2 * j]     = o0;
        ((float4*)out)[n * 16 + 2 * j + 1] = o1;
    }
}

extern "C" void kernel_launch(void* const* d_in, const int* in_sizes, int n_in,
                              void* d_out, int out_size) {
    // order: t, h, edge_index, edge_attr, W, att_src, att_dst,
    //        W_edge, att_edge, bias, ln_gamma, ln_beta
    const float* h        = (const float*)d_in[1];
    const void*  ei       = d_in[2];
    const float* attr     = (const float*)d_in[3];
    const float* W        = (const float*)d_in[4];
    const float* att_src  = (const float*)d_in[5];
    const float* att_dst  = (const float*)d_in[6];
    const float* W_edge   = (const float*)d_in[7];
    const float* att_edge = (const float*)d_in[8];
    const float* bias     = (const float*)d_in[9];
    const float* gamma    = (const float*)d_in[10];
    const float* beta     = (const float*)d_in[11];
    float* out = (float*)d_out;

    k_init   <<<197, 256>>>((const unsigned*)ei);
    k_prep   <<<(N_EDGES + 255) / 256, 256>>>(ei);
    k_scan1  <<<NB_SCAN, 1024>>>();
    k_scanB  <<<NB_SCAN, 1024>>>();
    k_wconv  <<<65, 256>>>(W, W_edge, att_edge);
    k_gemm   <<<(N_NODES + 31) / 32, 256>>>(h, att_src, att_dst);
    k_scatter<<<(N_EDGES + 255) / 256, 256>>>(attr);
    k_node   <<<N_NODES / 8, 256>>>(out, bias, gamma, beta);
}

// round 7
// speedup vs baseline: 1.2137x; 1.0431x over previous
#include <cuda_runtime.h>
#include <cuda_fp16.h>

#define N_NODES 50000
#define N_EDGES 800000
#define NB1 196             // ceil(50000/256)
#define PREP_EDGE_BLOCKS 3125   // 800000/256 exactly

// ---------------- scratch (static device globals; no allocation) ----------------
__device__ __align__(16) int   g_src[N_EDGES];
__device__ __align__(16) int   g_dst[N_EDGES];
__device__ __align__(16) int   g_rank[N_EDGES];
__device__ int   g_cnt[N_NODES];            // invariant: all-zero at kernel_launch entry
__device__ int   g_scan[NB1 * 256];
__device__ int   g_btot[NB1];
__device__ int   g_off[N_NODES + 1];
__device__ __align__(16) int     g_ssrc[N_EDGES];
__device__ __align__(16) float   g_salpha[N_EDGES * 4];    // full leaky logits, 12.8 MB
__device__ __align__(16) __half2 g_x2[N_NODES * 128];      // x in fp16, 25.6 MB
__device__ __align__(16) float   g_asrc[N_NODES * 4];
__device__ __align__(16) float   g_adst[N_NODES * 4];
__device__ __align__(16) __half  g_WhT[256 * 64];          // W transposed [n][k], fp16
__device__ float g_v[12];                                  // [edim*4 + head]

// ====== K1: prep (block-local dtype detect + unpack + hist/rank) + W convert + v_edge ======
__global__ void __launch_bounds__(256) k_prep(const unsigned* __restrict__ p,
                                              const float* __restrict__ W,
                                              const float* __restrict__ W_edge,
                                              const float* __restrict__ att_edge) {
    int b = blockIdx.x, t = threadIdx.x;
    if (b < PREP_EDGE_BLOCKS) {
        __shared__ unsigned wacc[8];
        __shared__ int s_is64;
        int e = b * 256 + t;                       // always < N_EDGES (exact tiling)
        unsigned acc = p[2 * e + 1];               // high word if int64, random value if int32
#pragma unroll
        for (int o = 16; o; o >>= 1) acc |= __shfl_xor_sync(0xffffffffu, acc, o);
        if ((t & 31) == 0) wacc[t >> 5] = acc;
        __syncthreads();
        if (t == 0) {
            unsigned a = 0;
#pragma unroll
            for (int i = 0; i < 8; i++) a |= wacc[i];
            s_is64 = (a == 0);
        }
        __syncthreads();
        int s, d;
        if (s_is64) {
            const long long* q = (const long long*)p;
            s = (int)q[e]; d = (int)q[N_EDGES + e];
        } else {
            const int* q = (const int*)p;
            s = q[e]; d = q[N_EDGES + e];
        }
        g_src[e] = s;
        g_dst[e] = d;
        g_rank[e] = atomicAdd(&g_cnt[d], 1);
    } else {
        int wb = b - PREP_EDGE_BLOCKS;
        if (wb < 64) {
            int j = wb * 256 + t;                  // j = n*64 + k
            int n = j >> 6, k = j & 63;
            g_WhT[j] = __float2half(W[k * 256 + n]);
        } else if (t < 192) {
            int pair = t >> 4, l = t & 15;         // pair = d*4 + h
            int d = pair >> 2, hh = pair & 3;
            float s = 0.0f;
#pragma unroll
            for (int q = 0; q < 4; q++)
                s += W_edge[d * 256 + hh * 64 + l + 16 * q] * att_edge[hh * 64 + l + 16 * q];
            s += __shfl_xor_sync(0xffffffffu, s, 8);
            s += __shfl_xor_sync(0xffffffffu, s, 4);
            s += __shfl_xor_sync(0xffffffffu, s, 2);
            s += __shfl_xor_sync(0xffffffffu, s, 1);
            if (l == 0) g_v[pair] = s;
        }
    }
}

// ====== K2: per-block inclusive scan (shuffle-based) ======
__global__ void __launch_bounds__(256) k_scan1() {
    __shared__ int ws[8];
    int b = blockIdx.x, t = threadIdx.x, lane = t & 31, w = t >> 5;
    int i = b * 256 + t;
    int x = (i < N_NODES) ? g_cnt[i] : 0;
#pragma unroll
    for (int o = 1; o < 32; o <<= 1) {
        int u = __shfl_up_sync(0xffffffffu, x, o);
        if (lane >= o) x += u;
    }
    if (lane == 31) ws[w] = x;
    __syncthreads();
    if (t < 8) {
        int y = ws[t];
#pragma unroll
        for (int o = 1; o < 8; o <<= 1) {
            int u = __shfl_up_sync(0x000000ffu, y, o);
            if (t >= o) y += u;
        }
        ws[t] = y;
    }
    __syncthreads();
    if (w) x += ws[w - 1];
    g_scan[i] = x;                       // inclusive within block
    if (t == 255) g_btot[b] = x;
}

// ====== K3: block offsets + write g_off + reset g_cnt ======
__global__ void __launch_bounds__(256) k_scanB() {
    __shared__ int ws[8];
    int b = blockIdx.x, t = threadIdx.x, lane = t & 31, w = t >> 5;
    int v = (t < b) ? g_btot[t] : 0;     // t<b<=195 < NB1, safe
#pragma unroll
    for (int o = 16; o; o >>= 1) v += __shfl_xor_sync(0xffffffffu, v, o);
    if (lane == 0) ws[w] = v;
    __syncthreads();
    int boff = 0;
#pragma unroll
    for (int k = 0; k < 8; k++) boff += ws[k];
    int i = b * 256 + t;
    if (i < N_NODES) {
        g_off[i] = g_scan[i] - g_cnt[i] + boff;   // exclusive prefix
        g_cnt[i] = 0;                             // restore invariant for next replay
    }
    if (b == 0 && t == 0) g_off[N_NODES] = N_EDGES;
}

// ---------------- tensor-core GEMM x = h @ W, fused a_src/a_dst ----------------
__device__ __forceinline__ void mma16816(float* c, unsigned a0, unsigned a1, unsigned a2,
                                         unsigned a3, unsigned b0, unsigned b1) {
    asm volatile(
        "mma.sync.aligned.m16n8k16.row.col.f32.f16.f16.f32 "
        "{%0,%1,%2,%3},{%4,%5,%6,%7},{%8,%9},{%0,%1,%2,%3};\n"
        : "+f"(c[0]), "+f"(c[1]), "+f"(c[2]), "+f"(c[3])
        : "r"(a0), "r"(a1), "r"(a2), "r"(a3), "r"(b0), "r"(b1));
}

__global__ void __launch_bounds__(256) k_gemm(const float* __restrict__ h,
                                              const float* __restrict__ att_src,
                                              const float* __restrict__ att_dst) {
    __shared__ __half As[32 * 72];
    __shared__ __half Ws[256 * 72];
    int t = threadIdx.x, lane = t & 31, w = t >> 5;
    int n0 = blockIdx.x * 32;

#pragma unroll
    for (int q = 0; q < 8; q++) {
        int j = t + 256 * q;
        int n = j >> 3, c = j & 7;
        *(uint4*)&Ws[n * 72 + c * 8] = ((const uint4*)g_WhT)[j];
    }
#pragma unroll
    for (int q = 0; q < 2; q++) {
        int i = t + 256 * q;
        int r = i >> 4, c4 = (i & 15) * 4;
        int node = n0 + r;
        float4 hv = (node < N_NODES) ? *(const float4*)&h[node * 64 + c4]
                                     : make_float4(0.f, 0.f, 0.f, 0.f);
        __half2 p0 = __floats2half2_rn(hv.x, hv.y);
        __half2 p1 = __floats2half2_rn(hv.z, hv.w);
        uint2 pk = {*(unsigned*)&p0, *(unsigned*)&p1};
        *(uint2*)&As[r * 72 + c4] = pk;
    }
    __syncthreads();

    int rt = w & 1, cg = w >> 1;
    int rbase = rt * 16;
    int qr = lane >> 2, qc = lane & 3;

    float acc[8][4];
#pragma unroll
    for (int i = 0; i < 8; i++)
#pragma unroll
        for (int j = 0; j < 4; j++) acc[i][j] = 0.f;

#pragma unroll
    for (int ks = 0; ks < 4; ks++) {
        int kk = ks * 16;
        unsigned a0 = *(const unsigned*)&As[(rbase + qr) * 72 + kk + 2 * qc];
        unsigned a1 = *(const unsigned*)&As[(rbase + qr + 8) * 72 + kk + 2 * qc];
        unsigned a2 = *(const unsigned*)&As[(rbase + qr) * 72 + kk + 8 + 2 * qc];
        unsigned a3 = *(const unsigned*)&As[(rbase + qr + 8) * 72 + kk + 8 + 2 * qc];
#pragma unroll
        for (int nf = 0; nf < 8; nf++) {
            int n = cg * 64 + nf * 8 + qr;
            unsigned b0 = *(const unsigned*)&Ws[n * 72 + kk + 2 * qc];
            unsigned b1 = *(const unsigned*)&Ws[n * 72 + kk + 8 + 2 * qc];
            mma16816(acc[nf], a0, a1, a2, a3, b0, b1);
        }
    }

    int node_lo = n0 + rbase + qr;
    int node_hi = node_lo + 8;
    float ps_lo = 0.f, ps_hi = 0.f, pd_lo = 0.f, pd_hi = 0.f;
#pragma unroll
    for (int nf = 0; nf < 8; nf++) {
        int col = cg * 64 + nf * 8 + 2 * qc;
        float2 sv = *(const float2*)&att_src[col];
        float2 dv = *(const float2*)&att_dst[col];
        ps_lo += acc[nf][0] * sv.x + acc[nf][1] * sv.y;
        ps_hi += acc[nf][2] * sv.x + acc[nf][3] * sv.y;
        pd_lo += acc[nf][0] * dv.x + acc[nf][1] * dv.y;
        pd_hi += acc[nf][2] * dv.x + acc[nf][3] * dv.y;
        if (node_lo < N_NODES)
            g_x2[node_lo * 128 + cg * 32 + nf * 4 + qc] = __floats2half2_rn(acc[nf][0], acc[nf][1]);
        if (node_hi < N_NODES)
            g_x2[node_hi * 128 + cg * 32 + nf * 4 + qc] = __floats2half2_rn(acc[nf][2], acc[nf][3]);
    }
    ps_lo += __shfl_xor_sync(0xffffffffu, ps_lo, 1);
    ps_lo += __shfl_xor_sync(0xffffffffu, ps_lo, 2);
    ps_hi += __shfl_xor_sync(0xffffffffu, ps_hi, 1);
    ps_hi += __shfl_xor_sync(0xffffffffu, ps_hi, 2);
    pd_lo += __shfl_xor_sync(0xffffffffu, pd_lo, 1);
    pd_lo += __shfl_xor_sync(0xffffffffu, pd_lo, 2);
    pd_hi += __shfl_xor_sync(0xffffffffu, pd_hi, 1);
    pd_hi += __shfl_xor_sync(0xffffffffu, pd_hi, 2);
    if (qc == 0) {
        if (node_lo < N_NODES) { g_asrc[node_lo * 4 + cg] = ps_lo; g_adst[node_lo * 4 + cg] = pd_lo; }
        if (node_hi < N_NODES) { g_asrc[node_hi * 4 + cg] = ps_hi; g_adst[node_hi * 4 + cg] = pd_hi; }
    }
}

// ---------------- scatter: 1 edge/thread, atomic-free via precomputed rank ----------------
__global__ void k_scatter(const float* __restrict__ attr) {
    int e = blockIdx.x * blockDim.x + threadIdx.x;
    if (e >= N_EDGES) return;
    int s = g_src[e], d = g_dst[e];
    int pos = g_off[d] + g_rank[e];
    float a0 = attr[e * 3 + 0], a1 = attr[e * 3 + 1], a2 = attr[e * 3 + 2];
    float4 as = *(const float4*)&g_asrc[s * 4];
    float4 ad = *(const float4*)&g_adst[d * 4];
    float4 o;
    o.x = as.x + ad.x + a0 * g_v[0] + a1 * g_v[4] + a2 * g_v[8];
    o.y = as.y + ad.y + a0 * g_v[1] + a1 * g_v[5] + a2 * g_v[9];
    o.z = as.z + ad.z + a0 * g_v[2] + a1 * g_v[6] + a2 * g_v[10];
    o.w = as.w + ad.w + a0 * g_v[3] + a1 * g_v[7] + a2 * g_v[11];
    o.x = o.x > 0.f ? o.x : 0.2f * o.x;
    o.y = o.y > 0.f ? o.y : 0.2f * o.y;
    o.z = o.z > 0.f ? o.z : 0.2f * o.z;
    o.w = o.w > 0.f ? o.w : 0.2f * o.w;
    *(float4*)&g_salpha[pos * 4] = o;
    g_ssrc[pos] = s;
}

// ---------------- warp per node: softmax + fp16 gather + LN + SiLU ----------------
__global__ void __launch_bounds__(256) k_node(float* __restrict__ out,
                                              const float* __restrict__ bias,
                                              const float* __restrict__ gamma,
                                              const float* __restrict__ beta) {
    int t = threadIdx.x, lane = t & 31, w = t >> 5;
    int n = blockIdx.x * 8 + w;
    int beg = g_off[n], end = g_off[n + 1];
    const float4* sal = (const float4*)g_salpha;

    // pass 1: segment max per head
    const float NINF = __int_as_float(0xff800000);
    float4 m = {NINF, NINF, NINF, NINF};
    for (int k = beg + lane; k < end; k += 32) {
        float4 a = sal[k];
        m.x = fmaxf(m.x, a.x); m.y = fmaxf(m.y, a.y);
        m.z = fmaxf(m.z, a.z); m.w = fmaxf(m.w, a.w);
    }
#pragma unroll
    for (int o = 16; o; o >>= 1) {
        m.x = fmaxf(m.x, __shfl_xor_sync(0xffffffffu, m.x, o));
        m.y = fmaxf(m.y, __shfl_xor_sync(0xffffffffu, m.y, o));
        m.z = fmaxf(m.z, __shfl_xor_sync(0xffffffffu, m.z, o));
        m.w = fmaxf(m.w, __shfl_xor_sync(0xffffffffu, m.w, o));
    }

    // pass 2: sum of exp
    float4 sm = {0.f, 0.f, 0.f, 0.f};
    for (int k = beg + lane; k < end; k += 32) {
        float4 a = sal[k];
        sm.x += expf(a.x - m.x); sm.y += expf(a.y - m.y);
        sm.z += expf(a.z - m.z); sm.w += expf(a.w - m.w);
    }
#pragma unroll
    for (int o = 16; o; o >>= 1) {
        sm.x += __shfl_xor_sync(0xffffffffu, sm.x, o);
        sm.y += __shfl_xor_sync(0xffffffffu, sm.y, o);
        sm.z += __shfl_xor_sync(0xffffffffu, sm.z, o);
        sm.w += __shfl_xor_sync(0xffffffffu, sm.w, o);
    }

    // per-lane head constants
    int hd = lane >> 3;
    float mh = (hd == 0) ? m.x : (hd == 1) ? m.y : (hd == 2) ? m.z : m.w;
    float sh = (hd == 0) ? sm.x : (hd == 1) ? sm.y : (hd == 2) ? sm.z : sm.w;
    float ih = 0.25f / (sh + 1e-16f);

    // pass 3: weighted gather of fp16 x
    float acc[8];
#pragma unroll
    for (int i = 0; i < 8; i++) acc[i] = 0.f;
    const uint4* xv4 = (const uint4*)g_x2;
    for (int k = beg; k < end; k++) {
        float4 a = sal[k];
        int s = g_ssrc[k];
        float ah = (hd == 0) ? a.x : (hd == 1) ? a.y : (hd == 2) ? a.z : a.w;
        float wgt = expf(ah - mh) * ih;
        uint4 xv = xv4[s * 32 + lane];
        const __half2* hp = (const __half2*)&xv;
#pragma unroll
        for (int i = 0; i < 4; i++) {
            float2 f = __half22float2(hp[i]);
            acc[2 * i]     += wgt * f.x;
            acc[2 * i + 1] += wgt * f.y;
        }
    }
#pragma unroll
    for (int i = 0; i < 8; i++) {
        acc[i] += __shfl_xor_sync(0xffffffffu, acc[i], 8);
        acc[i] += __shfl_xor_sync(0xffffffffu, acc[i], 16);
    }

    // LN + SiLU over 64 channels (lanes 0..7 write)
    int j = lane & 7;
    float4 b0 = ((const float4*)bias)[2 * j];
    float4 b1 = ((const float4*)bias)[2 * j + 1];
    float v[8] = {acc[0] + b0.x, acc[1] + b0.y, acc[2] + b0.z, acc[3] + b0.w,
                  acc[4] + b1.x, acc[5] + b1.y, acc[6] + b1.z, acc[7] + b1.w};
    float sum = 0.f, sq = 0.f;
#pragma unroll
    for (int i = 0; i < 8; i++) { sum += v[i]; sq += v[i] * v[i]; }
#pragma unroll
    for (int o = 4; o; o >>= 1) {
        sum += __shfl_xor_sync(0xffffffffu, sum, o);
        sq  += __shfl_xor_sync(0xffffffffu, sq, o);
    }
    float mu  = sum * (1.0f / 64.0f);
    float var = sq * (1.0f / 64.0f) - mu * mu;
    float inv = rsqrtf(var + 1e-5f);
    float4 g0 = ((const float4*)gamma)[2 * j];
    float4 g1 = ((const float4*)gamma)[2 * j + 1];
    float4 e0 = ((const float4*)beta)[2 * j];
    float4 e1 = ((const float4*)beta)[2 * j + 1];
    float gg[8] = {g0.x, g0.y, g0.z, g0.w, g1.x, g1.y, g1.z, g1.w};
    float ee[8] = {e0.x, e0.y, e0.z, e0.w, e1.x, e1.y, e1.z, e1.w};
    float y[8];
#pragma unroll
    for (int i = 0; i < 8; i++) {
        float yy = (v[i] - mu) * inv * gg[i] + ee[i];
        y[i] = yy / (1.0f + expf(-yy));
    }
    if (lane < 8) {
        float4 o0 = {y[0], y[1], y[2], y[3]};
        float4 o1 = {y[4], y[5], y[6], y[7]};
        ((float4*)out)[n * 16 + 2 * j]     = o0;
        ((float4*)out)[n * 16 + 2 * j + 1] = o1;
    }
}

extern "C" void kernel_launch(void* const* d_in, const int* in_sizes, int n_in,
                              void* d_out, int out_size) {
    // order: t, h, edge_index, edge_attr, W, att_src, att_dst,
    //        W_edge, att_edge, bias, ln_gamma, ln_beta
    const float* h        = (const float*)d_in[1];
    const void*  ei       = d_in[2];
    const float* attr     = (const float*)d_in[3];
    const float* W        = (const float*)d_in[4];
    const float* att_src  = (const float*)d_in[5];
    const float* att_dst  = (const float*)d_in[6];
    const float* W_edge   = (const float*)d_in[7];
    const float* att_edge = (const float*)d_in[8];
    const float* bias     = (const float*)d_in[9];
    const float* gamma    = (const float*)d_in[10];
    const float* beta     = (const float*)d_in[11];
    float* out = (float*)d_out;

    k_prep   <<<PREP_EDGE_BLOCKS + 65, 256>>>((const unsigned*)ei, W, W_edge, att_edge);
    k_scan1  <<<NB1, 256>>>();
    k_scanB  <<<NB1, 256>>>();
    k_gemm   <<<(N_NODES + 31) / 32, 256>>>(h, att_src, att_dst);
    k_scatter<<<(N_EDGES + 255) / 256, 256>>>(attr);
    k_node   <<<N_NODES / 8, 256>>>(out, bias, gamma, beta);
}